// round 1
// baseline (speedup 1.0000x reference)
#include <cuda_runtime.h>
#include <math.h>

#define N_MAX 100000
#define CH 128
#define KVOL 27
#define BN_EPS 1e-5f

// ---------------- scratch (device globals; no runtime allocation) ----------
__device__ float g_h2 [(size_t)N_MAX * CH];
__device__ float g_x  [(size_t)N_MAX * CH];
__device__ float g_q  [(size_t)N_MAX * CH];
__device__ float g_v  [(size_t)N_MAX * CH];
__device__ float g_acc[(size_t)N_MAX * CH];
__device__ float g_npe[KVOL * CH];
__device__ float g_s1[8];        // sums/sumsq for BN1 (3 channels)
__device__ float g_s2[2 * CH];   // sums/sumsq for BN2 (128 channels)

// ---------------- init: zero stats + normalize pos_enc ---------------------
__global__ void init_kernel(const float* __restrict__ pos_enc) {
    int tid = threadIdx.x;                 // 256 threads, 1 block
    if (tid < 8)  g_s1[tid] = 0.f;
    if (tid < 256) g_s2[tid] = 0.f;
    if (tid < KVOL * 8) {                  // 216 (k,h) groups, 16 each
        const float* src = pos_enc + tid * 16;
        float v[16]; float s = 0.f;
#pragma unroll
        for (int i = 0; i < 16; i++) { v[i] = src[i]; s += v[i] * v[i]; }
        float inv = 1.f / fmaxf(sqrtf(s), 1e-12f);
#pragma unroll
        for (int i = 0; i < 16; i++) g_npe[tid * 16 + i] = v[i] * inv;
    }
}

// ---------------- stats for BN1 over h1 = points @ W1 ----------------------
__global__ void __launch_bounds__(256) stats1_kernel(
        const float* __restrict__ points, const float* __restrict__ W1, int n) {
    __shared__ float sh[6];
    if (threadIdx.x < 6) sh[threadIdx.x] = 0.f;
    __syncthreads();
    float w[9];
#pragma unroll
    for (int i = 0; i < 9; i++) w[i] = __ldg(&W1[i]);
    float s[3] = {0.f, 0.f, 0.f}, q[3] = {0.f, 0.f, 0.f};
    for (int i = blockIdx.x * blockDim.x + threadIdx.x; i < n;
         i += gridDim.x * blockDim.x) {
        float px = points[i * 3 + 0], py = points[i * 3 + 1], pz = points[i * 3 + 2];
#pragma unroll
        for (int j = 0; j < 3; j++) {
            float h = px * w[j] + py * w[3 + j] + pz * w[6 + j];
            s[j] += h; q[j] += h * h;
        }
    }
#pragma unroll
    for (int o = 16; o; o >>= 1) {
#pragma unroll
        for (int j = 0; j < 3; j++) {
            s[j] += __shfl_down_sync(0xFFFFFFFFu, s[j], o);
            q[j] += __shfl_down_sync(0xFFFFFFFFu, q[j], o);
        }
    }
    if ((threadIdx.x & 31) == 0) {
#pragma unroll
        for (int j = 0; j < 3; j++) {
            atomicAdd(&sh[j], s[j]);
            atomicAdd(&sh[3 + j], q[j]);
        }
    }
    __syncthreads();
    if (threadIdx.x < 6) atomicAdd(&g_s1[threadIdx.x], sh[threadIdx.x]);
}

// ---------------- h2 = relu(bn1(points@W1)) @ W2, + BN2 stats --------------
#define H2_PB 128
__global__ void __launch_bounds__(256) h2_kernel(
        const float* __restrict__ points, const float* __restrict__ W1,
        const float* __restrict__ g1, const float* __restrict__ b1,
        const float* __restrict__ W2, int n) {
    __shared__ float ssum[CH], ssq[CH];
    int tid = threadIdx.x;
    if (tid < CH) { ssum[tid] = 0.f; ssq[tid] = 0.f; }
    __syncthreads();

    float w1[9];
#pragma unroll
    for (int i = 0; i < 9; i++) w1[i] = __ldg(&W1[i]);
    float invn = 1.f / (float)n;
    float sc[3], shf[3];
#pragma unroll
    for (int j = 0; j < 3; j++) {
        float mu  = g_s1[j] * invn;
        float var = g_s1[3 + j] * invn - mu * mu;
        float rs  = rsqrtf(var + BN_EPS);
        float s   = rs * __ldg(&g1[j]);
        sc[j] = s; shf[j] = __ldg(&b1[j]) - mu * s;
    }
    int lane = tid & 31, wid = tid >> 5;
    int c0 = lane * 4;
    float w2a[4], w2b[4], w2c[4];
#pragma unroll
    for (int i = 0; i < 4; i++) {
        w2a[i] = __ldg(&W2[0 * CH + c0 + i]);
        w2b[i] = __ldg(&W2[1 * CH + c0 + i]);
        w2c[i] = __ldg(&W2[2 * CH + c0 + i]);
    }
    float ls[4] = {0, 0, 0, 0}, lq[4] = {0, 0, 0, 0};
    int base = blockIdx.x * H2_PB;
    int nend = min(base + H2_PB, n);
    for (int p = base + wid; p < nend; p += 8) {
        float px = __ldg(&points[p * 3 + 0]);
        float py = __ldg(&points[p * 3 + 1]);
        float pz = __ldg(&points[p * 3 + 2]);
        float a[3];
#pragma unroll
        for (int j = 0; j < 3; j++) {
            float h = px * w1[j] + py * w1[3 + j] + pz * w1[6 + j];
            a[j] = fmaxf(h * sc[j] + shf[j], 0.f);
        }
        float o[4];
#pragma unroll
        for (int i = 0; i < 4; i++) {
            o[i] = a[0] * w2a[i] + a[1] * w2b[i] + a[2] * w2c[i];
            ls[i] += o[i]; lq[i] += o[i] * o[i];
        }
        float4 o4 = make_float4(o[0], o[1], o[2], o[3]);
        *(float4*)&g_h2[(size_t)p * CH + c0] = o4;
    }
#pragma unroll
    for (int i = 0; i < 4; i++) {
        atomicAdd(&ssum[c0 + i], ls[i]);
        atomicAdd(&ssq[c0 + i], lq[i]);
    }
    __syncthreads();
    if (tid < CH) {
        atomicAdd(&g_s2[tid], ssum[tid]);
        atomicAdd(&g_s2[CH + tid], ssq[tid]);
    }
}

// ---------------- generic 128-wide GEMM: C = f(A) @ B + bias, epilogue -----
// MODE 0: C = A@B + bias
// MODE 1: A' = relu(bn2(A)); C = A'@B + bias + extra   (extra = feats)
// MODE 2: C = l2norm_per16(A@B + bias)
#define GEMM_SMEM_BYTES ((16384 + 64 * 132 + 256) * 4)
template <int MODE>
__global__ void __launch_bounds__(256) gemm_kernel(
        const float* __restrict__ A, const float* __restrict__ B,
        const float* __restrict__ bias, float* __restrict__ C,
        const float* __restrict__ extra, const float* __restrict__ gamma,
        const float* __restrict__ beta, int nrows) {
    extern __shared__ float sm[];
    float* Bs   = sm;                    // 128*128
    float* As   = sm + 16384;            // 64*132 (padded)
    float* s_sc = As + 64 * 132;         // 128
    float* s_sh = s_sc + CH;             // 128

    int tid  = threadIdx.x;
    int row0 = blockIdx.x * 64;

    // load full B panel
#pragma unroll
    for (int i = 0; i < 16; i++) {
        int li = i * 256 + tid;
        ((float4*)Bs)[li] = __ldg(((const float4*)B) + li);
    }
    if (MODE == 1 && tid < CH) {
        float invn = 1.f / (float)nrows;
        float mu  = g_s2[tid] * invn;
        float var = g_s2[CH + tid] * invn - mu * mu;
        float rs  = rsqrtf(var + BN_EPS);
        float s   = rs * __ldg(&gamma[tid]);
        s_sc[tid] = s; s_sh[tid] = __ldg(&beta[tid]) - mu * s;
    }
    __syncthreads();

    // load A tile (64 rows)
#pragma unroll
    for (int i = 0; i < 8; i++) {
        int li = i * 256 + tid;          // float4 index, 2048 total
        int r  = li >> 5;
        int c  = (li & 31) << 2;
        float4 a = make_float4(0.f, 0.f, 0.f, 0.f);
        if (row0 + r < nrows)
            a = __ldg((const float4*)(A + (size_t)(row0 + r) * CH + c));
        if (MODE == 1) {
            a.x = fmaxf(a.x * s_sc[c + 0] + s_sh[c + 0], 0.f);
            a.y = fmaxf(a.y * s_sc[c + 1] + s_sh[c + 1], 0.f);
            a.z = fmaxf(a.z * s_sc[c + 2] + s_sh[c + 2], 0.f);
            a.w = fmaxf(a.w * s_sc[c + 3] + s_sh[c + 3], 0.f);
        }
        *(float4*)&As[r * 132 + c] = a;
    }
    __syncthreads();

    int tx = tid & 15, ty = tid >> 4;
    float acc[4][8];
#pragma unroll
    for (int r = 0; r < 4; r++)
#pragma unroll
        for (int c = 0; c < 8; c++) acc[r][c] = 0.f;

    const float* Ap = As + ty * 4 * 132;
#pragma unroll 4
    for (int k = 0; k < 128; k++) {
        float4 b0 = *(const float4*)&Bs[k * CH + (tx << 2)];
        float4 b1 = *(const float4*)&Bs[k * CH + 64 + (tx << 2)];
        float a[4] = {Ap[k], Ap[132 + k], Ap[264 + k], Ap[396 + k]};
        float b[8] = {b0.x, b0.y, b0.z, b0.w, b1.x, b1.y, b1.z, b1.w};
#pragma unroll
        for (int r = 0; r < 4; r++)
#pragma unroll
            for (int c = 0; c < 8; c++) acc[r][c] = fmaf(a[r], b[c], acc[r][c]);
    }

    float4 bias0 = __ldg((const float4*)(bias + (tx << 2)));
    float4 bias1 = __ldg((const float4*)(bias + 64 + (tx << 2)));
#pragma unroll
    for (int rr = 0; rr < 4; rr++) {
        int row = row0 + ty * 4 + rr;
        bool ok = row < nrows;
        float4 o0 = make_float4(acc[rr][0] + bias0.x, acc[rr][1] + bias0.y,
                                acc[rr][2] + bias0.z, acc[rr][3] + bias0.w);
        float4 o1 = make_float4(acc[rr][4] + bias1.x, acc[rr][5] + bias1.y,
                                acc[rr][6] + bias1.z, acc[rr][7] + bias1.w);
        if (MODE == 1 && ok) {
            float4 f0 = __ldg((const float4*)(extra + (size_t)row * CH + (tx << 2)));
            float4 f1 = __ldg((const float4*)(extra + (size_t)row * CH + 64 + (tx << 2)));
            o0.x += f0.x; o0.y += f0.y; o0.z += f0.z; o0.w += f0.w;
            o1.x += f1.x; o1.y += f1.y; o1.z += f1.z; o1.w += f1.w;
        }
        if (MODE == 2) {
            // l2-norm over groups of 16 channels: each thread holds 4 cols of a
            // head; lanes (tx, tx^1, tx^2, tx^3)?? -> cols tx*4: head = tx/4,
            // partner lanes are tx^1 and tx^2 within same head.
            float s0 = o0.x * o0.x + o0.y * o0.y + o0.z * o0.z + o0.w * o0.w;
            float s1 = o1.x * o1.x + o1.y * o1.y + o1.z * o1.z + o1.w * o1.w;
            s0 += __shfl_xor_sync(0xFFFFFFFFu, s0, 1);
            s0 += __shfl_xor_sync(0xFFFFFFFFu, s0, 2);
            s1 += __shfl_xor_sync(0xFFFFFFFFu, s1, 1);
            s1 += __shfl_xor_sync(0xFFFFFFFFu, s1, 2);
            float i0 = 1.f / fmaxf(sqrtf(s0), 1e-12f);
            float i1 = 1.f / fmaxf(sqrtf(s1), 1e-12f);
            o0.x *= i0; o0.y *= i0; o0.z *= i0; o0.w *= i0;
            o1.x *= i1; o1.y *= i1; o1.z *= i1; o1.w *= i1;
        }
        if (ok) {
            *(float4*)&C[(size_t)row * CH + (tx << 2)] = o0;
            *(float4*)&C[(size_t)row * CH + 64 + (tx << 2)] = o1;
        }
    }
}

// ---------------- scatter: warp per map entry -------------------------------
__global__ void __launch_bounds__(256) scatter_kernel(
        const int* __restrict__ kq, int M) {
    int gw = (blockIdx.x * blockDim.x + threadIdx.x) >> 5;
    if (gw >= M) return;
    int lane = threadIdx.x & 31;
    int kk = __ldg(&kq[gw]);
    int qi = __ldg(&kq[M + gw]);
    int key  = kk / KVOL;
    int kern = kk - key * KVOL;
    float4 q4 = *(const float4*)&g_q[(size_t)qi * CH + lane * 4];
    float4 p4 = *(const float4*)&g_npe[kern * CH + lane * 4];
    float s = q4.x * p4.x + q4.y * p4.y + q4.z * p4.z + q4.w * p4.w;
    s += __shfl_xor_sync(0xFFFFFFFFu, s, 1);
    s += __shfl_xor_sync(0xFFFFFFFFu, s, 2);   // head-local dot (16 ch = 4 lanes)
    float4 v4 = *(const float4*)&g_v[(size_t)key * CH + lane * 4];
    float* dst = &g_acc[(size_t)qi * CH + lane * 4];
    atomicAdd(dst + 0, s * v4.x);
    atomicAdd(dst + 1, s * v4.y);
    atomicAdd(dst + 2, s * v4.z);
    atomicAdd(dst + 3, s * v4.w);
}

// ---------------- host launch ----------------------------------------------
extern "C" void kernel_launch(void* const* d_in, const int* in_sizes, int n_in,
                              void* d_out, int out_size) {
    const float* feats   = (const float*)d_in[0];
    const float* points  = (const float*)d_in[1];
    const int*   kq      = (const int*)d_in[2];
    const float* W1 = (const float*)d_in[3];
    const float* g1 = (const float*)d_in[4];
    const float* b1 = (const float*)d_in[5];
    const float* W2 = (const float*)d_in[6];
    const float* g2 = (const float*)d_in[7];
    const float* b2 = (const float*)d_in[8];
    const float* W3 = (const float*)d_in[9];
    const float* b3 = (const float*)d_in[10];
    const float* Wq = (const float*)d_in[11];
    const float* bq = (const float*)d_in[12];
    const float* Wv = (const float*)d_in[13];
    const float* bv = (const float*)d_in[14];
    const float* pos_enc = (const float*)d_in[15];
    const float* Wo = (const float*)d_in[16];
    const float* bo = (const float*)d_in[17];

    int N = in_sizes[0] / CH;
    int M = in_sizes[2] / 2;

    cudaFuncSetAttribute((const void*)gemm_kernel<0>,
                         cudaFuncAttributeMaxDynamicSharedMemorySize, GEMM_SMEM_BYTES);
    cudaFuncSetAttribute((const void*)gemm_kernel<1>,
                         cudaFuncAttributeMaxDynamicSharedMemorySize, GEMM_SMEM_BYTES);
    cudaFuncSetAttribute((const void*)gemm_kernel<2>,
                         cudaFuncAttributeMaxDynamicSharedMemorySize, GEMM_SMEM_BYTES);

    // pointers to scratch buffers (for memset)
    void* accp = nullptr;
    cudaGetSymbolAddress(&accp, g_acc);
    cudaMemsetAsync(accp, 0, (size_t)N * CH * sizeof(float), 0);

    float* h2p; float* xp; float* qp; float* vp; float* ap;
    { void* t; cudaGetSymbolAddress(&t, g_h2);  h2p = (float*)t; }
    { void* t; cudaGetSymbolAddress(&t, g_x);   xp  = (float*)t; }
    { void* t; cudaGetSymbolAddress(&t, g_q);   qp  = (float*)t; }
    { void* t; cudaGetSymbolAddress(&t, g_v);   vp  = (float*)t; }
    ap = (float*)accp;

    init_kernel<<<1, 256>>>(pos_enc);
    stats1_kernel<<<256, 256>>>(points, W1, N);
    h2_kernel<<<(N + H2_PB - 1) / H2_PB, 256>>>(points, W1, g1, b1, W2, N);

    int gblocks = (N + 63) / 64;
    // x = relu(bn2(h2)) @ W3 + b3 + feats
    gemm_kernel<1><<<gblocks, 256, GEMM_SMEM_BYTES>>>(h2p, W3, b3, xp, feats, g2, b2, N);
    // q = l2norm16(x @ Wq + bq)
    gemm_kernel<2><<<gblocks, 256, GEMM_SMEM_BYTES>>>(xp, Wq, bq, qp, nullptr, nullptr, nullptr, N);
    // v = x @ Wv + bv
    gemm_kernel<0><<<gblocks, 256, GEMM_SMEM_BYTES>>>(xp, Wv, bv, vp, nullptr, nullptr, nullptr, N);

    // attention scatter
    int sblocks = (M + 7) / 8;
    scatter_kernel<<<sblocks, 256>>>(kq, M);

    // out = acc @ Wo + bo
    gemm_kernel<0><<<gblocks, 256, GEMM_SMEM_BYTES>>>(ap, Wo, bo, (float*)d_out,
                                                      nullptr, nullptr, nullptr, N);
}

// round 2
// speedup vs baseline: 1.3326x; 1.3326x over previous
#include <cuda_runtime.h>
#include <math.h>

#define N_MAX 100000
#define M_MAX 1600000
#define CH 128
#define KVOL 27
#define BN_EPS 1e-5f

// ---------------- scratch (device globals; no runtime allocation) ----------
__device__ float g_h2 [(size_t)N_MAX * CH];
__device__ float g_x  [(size_t)N_MAX * CH];
__device__ float g_q  [(size_t)N_MAX * CH];
__device__ float g_v  [(size_t)N_MAX * CH];
__device__ float g_acc[(size_t)N_MAX * CH];
__device__ float g_npe[KVOL * CH];
__device__ float g_s1[8];        // sums/sumsq for BN1 (3 channels)
__device__ float g_s2[2 * CH];   // sums/sumsq for BN2 (128 channels)
__device__ int   g_cnt[N_MAX];   // per-query entry count (histogram)
__device__ int   g_off[N_MAX];   // per-query exclusive offset
__device__ int   g_cur[N_MAX];   // placement cursors
__device__ int   g_sorted[M_MAX];// kk = key*27+kern, segment-sorted by q

// ---------------- packed f32x2 helpers --------------------------------------
__device__ __forceinline__ unsigned long long pack2(float x) {
    unsigned long long r;
    asm("mov.b64 %0, {%1, %1};" : "=l"(r) : "f"(x));
    return r;
}
__device__ __forceinline__ void fma2(unsigned long long& d,
                                     unsigned long long a,
                                     unsigned long long b) {
    asm("fma.rn.f32x2 %0, %1, %2, %0;" : "+l"(d) : "l"(a), "l"(b));
}
__device__ __forceinline__ float2 unpack2(unsigned long long v) {
    float2 r;
    asm("mov.b64 {%0, %1}, %2;" : "=f"(r.x), "=f"(r.y) : "l"(v));
    return r;
}

// ---------------- init: zero stats + normalize pos_enc ---------------------
__global__ void init_kernel(const float* __restrict__ pos_enc) {
    int tid = threadIdx.x;                 // 256 threads, 1 block
    if (tid < 8)  g_s1[tid] = 0.f;
    if (tid < 256) g_s2[tid] = 0.f;
    if (tid < KVOL * 8) {                  // 216 (k,h) groups, 16 each
        const float* src = pos_enc + tid * 16;
        float v[16]; float s = 0.f;
#pragma unroll
        for (int i = 0; i < 16; i++) { v[i] = src[i]; s += v[i] * v[i]; }
        float inv = 1.f / fmaxf(sqrtf(s), 1e-12f);
#pragma unroll
        for (int i = 0; i < 16; i++) g_npe[tid * 16 + i] = v[i] * inv;
    }
}

// ---------------- stats for BN1 over h1 = points @ W1 ----------------------
__global__ void __launch_bounds__(256) stats1_kernel(
        const float* __restrict__ points, const float* __restrict__ W1, int n) {
    __shared__ float sh[6];
    if (threadIdx.x < 6) sh[threadIdx.x] = 0.f;
    __syncthreads();
    float w[9];
#pragma unroll
    for (int i = 0; i < 9; i++) w[i] = __ldg(&W1[i]);
    float s[3] = {0.f, 0.f, 0.f}, q[3] = {0.f, 0.f, 0.f};
    for (int i = blockIdx.x * blockDim.x + threadIdx.x; i < n;
         i += gridDim.x * blockDim.x) {
        float px = points[i * 3 + 0], py = points[i * 3 + 1], pz = points[i * 3 + 2];
#pragma unroll
        for (int j = 0; j < 3; j++) {
            float h = px * w[j] + py * w[3 + j] + pz * w[6 + j];
            s[j] += h; q[j] += h * h;
        }
    }
#pragma unroll
    for (int o = 16; o; o >>= 1) {
#pragma unroll
        for (int j = 0; j < 3; j++) {
            s[j] += __shfl_down_sync(0xFFFFFFFFu, s[j], o);
            q[j] += __shfl_down_sync(0xFFFFFFFFu, q[j], o);
        }
    }
    if ((threadIdx.x & 31) == 0) {
#pragma unroll
        for (int j = 0; j < 3; j++) {
            atomicAdd(&sh[j], s[j]);
            atomicAdd(&sh[3 + j], q[j]);
        }
    }
    __syncthreads();
    if (threadIdx.x < 6) atomicAdd(&g_s1[threadIdx.x], sh[threadIdx.x]);
}

// ---------------- h2 = relu(bn1(points@W1)) @ W2, + BN2 stats --------------
#define H2_PB 128
__global__ void __launch_bounds__(256) h2_kernel(
        const float* __restrict__ points, const float* __restrict__ W1,
        const float* __restrict__ g1, const float* __restrict__ b1,
        const float* __restrict__ W2, int n) {
    __shared__ float ssum[CH], ssq[CH];
    int tid = threadIdx.x;
    if (tid < CH) { ssum[tid] = 0.f; ssq[tid] = 0.f; }
    __syncthreads();

    float w1[9];
#pragma unroll
    for (int i = 0; i < 9; i++) w1[i] = __ldg(&W1[i]);
    float invn = 1.f / (float)n;
    float sc[3], shf[3];
#pragma unroll
    for (int j = 0; j < 3; j++) {
        float mu  = g_s1[j] * invn;
        float var = g_s1[3 + j] * invn - mu * mu;
        float rs  = rsqrtf(var + BN_EPS);
        float s   = rs * __ldg(&g1[j]);
        sc[j] = s; shf[j] = __ldg(&b1[j]) - mu * s;
    }
    int lane = tid & 31, wid = tid >> 5;
    int c0 = lane * 4;
    float w2a[4], w2b[4], w2c[4];
#pragma unroll
    for (int i = 0; i < 4; i++) {
        w2a[i] = __ldg(&W2[0 * CH + c0 + i]);
        w2b[i] = __ldg(&W2[1 * CH + c0 + i]);
        w2c[i] = __ldg(&W2[2 * CH + c0 + i]);
    }
    float ls[4] = {0, 0, 0, 0}, lq[4] = {0, 0, 0, 0};
    int base = blockIdx.x * H2_PB;
    int nend = min(base + H2_PB, n);
    for (int p = base + wid; p < nend; p += 8) {
        float px = __ldg(&points[p * 3 + 0]);
        float py = __ldg(&points[p * 3 + 1]);
        float pz = __ldg(&points[p * 3 + 2]);
        float a[3];
#pragma unroll
        for (int j = 0; j < 3; j++) {
            float h = px * w1[j] + py * w1[3 + j] + pz * w1[6 + j];
            a[j] = fmaxf(h * sc[j] + shf[j], 0.f);
        }
        float o[4];
#pragma unroll
        for (int i = 0; i < 4; i++) {
            o[i] = a[0] * w2a[i] + a[1] * w2b[i] + a[2] * w2c[i];
            ls[i] += o[i]; lq[i] += o[i] * o[i];
        }
        float4 o4 = make_float4(o[0], o[1], o[2], o[3]);
        *(float4*)&g_h2[(size_t)p * CH + c0] = o4;
    }
#pragma unroll
    for (int i = 0; i < 4; i++) {
        atomicAdd(&ssum[c0 + i], ls[i]);
        atomicAdd(&ssq[c0 + i], lq[i]);
    }
    __syncthreads();
    if (tid < CH) {
        atomicAdd(&g_s2[tid], ssum[tid]);
        atomicAdd(&g_s2[CH + tid], ssq[tid]);
    }
}

// ---------------- generic 128-wide GEMM: C = f(A) @ B + bias, epilogue -----
// MODE 0: C = A@B + bias
// MODE 1: A' = relu(bn2(A)); C = A'@B + bias + extra   (extra = feats)
// MODE 2: C = l2norm_per16(A@B + bias)
#define GEMM_SMEM_BYTES ((16384 + 64 * 132 + 256) * 4)
template <int MODE>
__global__ void __launch_bounds__(256) gemm_kernel(
        const float* __restrict__ A, const float* __restrict__ B,
        const float* __restrict__ bias, float* __restrict__ C,
        const float* __restrict__ extra, const float* __restrict__ gamma,
        const float* __restrict__ beta, int nrows) {
    extern __shared__ float sm[];
    float* Bs   = sm;                    // 128*128
    float* As   = sm + 16384;            // 64*132 (padded)
    float* s_sc = As + 64 * 132;         // 128
    float* s_sh = s_sc + CH;             // 128

    int tid  = threadIdx.x;
    int row0 = blockIdx.x * 64;

    // load full B panel
#pragma unroll
    for (int i = 0; i < 16; i++) {
        int li = i * 256 + tid;
        ((float4*)Bs)[li] = __ldg(((const float4*)B) + li);
    }
    if (MODE == 1 && tid < CH) {
        float invn = 1.f / (float)nrows;
        float mu  = g_s2[tid] * invn;
        float var = g_s2[CH + tid] * invn - mu * mu;
        float rs  = rsqrtf(var + BN_EPS);
        float s   = rs * __ldg(&gamma[tid]);
        s_sc[tid] = s; s_sh[tid] = __ldg(&beta[tid]) - mu * s;
    }
    __syncthreads();

    // load A tile (64 rows)
#pragma unroll
    for (int i = 0; i < 8; i++) {
        int li = i * 256 + tid;          // float4 index, 2048 total
        int r  = li >> 5;
        int c  = (li & 31) << 2;
        float4 a = make_float4(0.f, 0.f, 0.f, 0.f);
        if (row0 + r < nrows)
            a = __ldg((const float4*)(A + (size_t)(row0 + r) * CH + c));
        if (MODE == 1) {
            a.x = fmaxf(a.x * s_sc[c + 0] + s_sh[c + 0], 0.f);
            a.y = fmaxf(a.y * s_sc[c + 1] + s_sh[c + 1], 0.f);
            a.z = fmaxf(a.z * s_sc[c + 2] + s_sh[c + 2], 0.f);
            a.w = fmaxf(a.w * s_sc[c + 3] + s_sh[c + 3], 0.f);
        }
        *(float4*)&As[r * 132 + c] = a;
    }
    __syncthreads();

    int tx = tid & 15, ty = tid >> 4;
    // packed f32x2 accumulators: acc2[r][c] holds cols (pair) for row r
    unsigned long long acc2[4][4];
#pragma unroll
    for (int r = 0; r < 4; r++)
#pragma unroll
        for (int c = 0; c < 4; c++) acc2[r][c] = 0ull;

    const float* Ap = As + ty * 4 * 132;
#pragma unroll 4
    for (int k = 0; k < 128; k++) {
        ulonglong2 b0 = *(const ulonglong2*)&Bs[k * CH + (tx << 2)];
        ulonglong2 b1 = *(const ulonglong2*)&Bs[k * CH + 64 + (tx << 2)];
        unsigned long long bb[4] = {b0.x, b0.y, b1.x, b1.y};
#pragma unroll
        for (int r = 0; r < 4; r++) {
            unsigned long long aa = pack2(Ap[r * 132 + k]);
#pragma unroll
            for (int c = 0; c < 4; c++) fma2(acc2[r][c], aa, bb[c]);
        }
    }

    float4 bias0 = __ldg((const float4*)(bias + (tx << 2)));
    float4 bias1 = __ldg((const float4*)(bias + 64 + (tx << 2)));
#pragma unroll
    for (int rr = 0; rr < 4; rr++) {
        int row = row0 + ty * 4 + rr;
        bool ok = row < nrows;
        float2 u0 = unpack2(acc2[rr][0]);
        float2 u1 = unpack2(acc2[rr][1]);
        float2 u2 = unpack2(acc2[rr][2]);
        float2 u3 = unpack2(acc2[rr][3]);
        float4 o0 = make_float4(u0.x + bias0.x, u0.y + bias0.y,
                                u1.x + bias0.z, u1.y + bias0.w);
        float4 o1 = make_float4(u2.x + bias1.x, u2.y + bias1.y,
                                u3.x + bias1.z, u3.y + bias1.w);
        if (MODE == 1 && ok) {
            float4 f0 = __ldg((const float4*)(extra + (size_t)row * CH + (tx << 2)));
            float4 f1 = __ldg((const float4*)(extra + (size_t)row * CH + 64 + (tx << 2)));
            o0.x += f0.x; o0.y += f0.y; o0.z += f0.z; o0.w += f0.w;
            o1.x += f1.x; o1.y += f1.y; o1.z += f1.z; o1.w += f1.w;
        }
        if (MODE == 2) {
            // l2-norm over 16-channel heads: lanes tx^1, tx^2 share a head
            float s0 = o0.x * o0.x + o0.y * o0.y + o0.z * o0.z + o0.w * o0.w;
            float s1 = o1.x * o1.x + o1.y * o1.y + o1.z * o1.z + o1.w * o1.w;
            s0 += __shfl_xor_sync(0xFFFFFFFFu, s0, 1);
            s0 += __shfl_xor_sync(0xFFFFFFFFu, s0, 2);
            s1 += __shfl_xor_sync(0xFFFFFFFFu, s1, 1);
            s1 += __shfl_xor_sync(0xFFFFFFFFu, s1, 2);
            float i0 = 1.f / fmaxf(sqrtf(s0), 1e-12f);
            float i1 = 1.f / fmaxf(sqrtf(s1), 1e-12f);
            o0.x *= i0; o0.y *= i0; o0.z *= i0; o0.w *= i0;
            o1.x *= i1; o1.y *= i1; o1.z *= i1; o1.w *= i1;
        }
        if (ok) {
            *(float4*)&C[(size_t)row * CH + (tx << 2)] = o0;
            *(float4*)&C[(size_t)row * CH + 64 + (tx << 2)] = o1;
        }
    }
}

// ---------------- counting sort of map entries by q_idx --------------------
__global__ void __launch_bounds__(256) hist_kernel(const int* __restrict__ kq, int M) {
    int i = blockIdx.x * blockDim.x + threadIdx.x;
    if (i < M) atomicAdd(&g_cnt[__ldg(&kq[M + i])], 1);
}

#define SCAN_T 1024
__global__ void __launch_bounds__(SCAN_T) scan_kernel(int n) {
    __shared__ int ssum[SCAN_T];
    int t = threadIdx.x;
    int chunk = (n + SCAN_T - 1) / SCAN_T;
    int beg = t * chunk, end = min(beg + chunk, n);
    int s = 0;
    for (int i = beg; i < end; i++) s += g_cnt[i];
    ssum[t] = s;
    __syncthreads();
    for (int o = 1; o < SCAN_T; o <<= 1) {
        int v = (t >= o) ? ssum[t - o] : 0;
        __syncthreads();
        ssum[t] += v;
        __syncthreads();
    }
    int run = (t == 0) ? 0 : ssum[t - 1];
    for (int i = beg; i < end; i++) {
        g_off[i] = run; g_cur[i] = run;
        run += g_cnt[i];
    }
}

__global__ void __launch_bounds__(256) place_kernel(const int* __restrict__ kq, int M) {
    int i = blockIdx.x * blockDim.x + threadIdx.x;
    if (i < M) {
        int q = __ldg(&kq[M + i]);
        int pos = atomicAdd(&g_cur[q], 1);
        g_sorted[pos] = __ldg(&kq[i]);
    }
}

// ---------------- segment gather: warp per query, no atomics ---------------
__global__ void __launch_bounds__(256) gather_kernel(int n) {
    int gw = (blockIdx.x * blockDim.x + threadIdx.x) >> 5;
    if (gw >= n) return;
    int lane = threadIdx.x & 31;
    int beg = __ldg(&g_off[gw]);
    int cnt = __ldg(&g_cnt[gw]);
    float4 qv = *(const float4*)&g_q[(size_t)gw * CH + lane * 4];
    float4 acc = make_float4(0.f, 0.f, 0.f, 0.f);
#pragma unroll 2
    for (int i = 0; i < cnt; i++) {
        int e = __ldg(&g_sorted[beg + i]);
        int key = e / KVOL;
        int kern = e - key * KVOL;
        float4 p = *(const float4*)&g_npe[kern * CH + lane * 4];
        float s = qv.x * p.x + qv.y * p.y + qv.z * p.z + qv.w * p.w;
        s += __shfl_xor_sync(0xFFFFFFFFu, s, 1);
        s += __shfl_xor_sync(0xFFFFFFFFu, s, 2);   // 16-ch head dot
        float4 v = __ldg((const float4*)&g_v[(size_t)key * CH + lane * 4]);
        acc.x = fmaf(s, v.x, acc.x);
        acc.y = fmaf(s, v.y, acc.y);
        acc.z = fmaf(s, v.z, acc.z);
        acc.w = fmaf(s, v.w, acc.w);
    }
    *(float4*)&g_acc[(size_t)gw * CH + lane * 4] = acc;
}

// ---------------- host launch ----------------------------------------------
extern "C" void kernel_launch(void* const* d_in, const int* in_sizes, int n_in,
                              void* d_out, int out_size) {
    const float* feats   = (const float*)d_in[0];
    const float* points  = (const float*)d_in[1];
    const int*   kq      = (const int*)d_in[2];
    const float* W1 = (const float*)d_in[3];
    const float* g1 = (const float*)d_in[4];
    const float* b1 = (const float*)d_in[5];
    const float* W2 = (const float*)d_in[6];
    const float* g2 = (const float*)d_in[7];
    const float* b2 = (const float*)d_in[8];
    const float* W3 = (const float*)d_in[9];
    const float* b3 = (const float*)d_in[10];
    const float* Wq = (const float*)d_in[11];
    const float* bq = (const float*)d_in[12];
    const float* Wv = (const float*)d_in[13];
    const float* bv = (const float*)d_in[14];
    const float* pos_enc = (const float*)d_in[15];
    const float* Wo = (const float*)d_in[16];
    const float* bo = (const float*)d_in[17];

    int N = in_sizes[0] / CH;
    int M = in_sizes[2] / 2;

    cudaFuncSetAttribute((const void*)gemm_kernel<0>,
                         cudaFuncAttributeMaxDynamicSharedMemorySize, GEMM_SMEM_BYTES);
    cudaFuncSetAttribute((const void*)gemm_kernel<1>,
                         cudaFuncAttributeMaxDynamicSharedMemorySize, GEMM_SMEM_BYTES);
    cudaFuncSetAttribute((const void*)gemm_kernel<2>,
                         cudaFuncAttributeMaxDynamicSharedMemorySize, GEMM_SMEM_BYTES);

    float* h2p; float* xp; float* qp; float* vp; float* ap;
    { void* t; cudaGetSymbolAddress(&t, g_h2);  h2p = (float*)t; }
    { void* t; cudaGetSymbolAddress(&t, g_x);   xp  = (float*)t; }
    { void* t; cudaGetSymbolAddress(&t, g_q);   qp  = (float*)t; }
    { void* t; cudaGetSymbolAddress(&t, g_v);   vp  = (float*)t; }
    { void* t; cudaGetSymbolAddress(&t, g_acc); ap  = (float*)t; }
    void* cntp = nullptr;
    cudaGetSymbolAddress(&cntp, g_cnt);
    cudaMemsetAsync(cntp, 0, (size_t)N * sizeof(int), 0);

    init_kernel<<<1, 256>>>(pos_enc);
    stats1_kernel<<<256, 256>>>(points, W1, N);
    h2_kernel<<<(N + H2_PB - 1) / H2_PB, 256>>>(points, W1, g1, b1, W2, N);

    // counting sort (overlaps with MLP/GEMM stream order; independent work)
    hist_kernel<<<(M + 255) / 256, 256>>>(kq, M);
    scan_kernel<<<1, SCAN_T>>>(N);
    place_kernel<<<(M + 255) / 256, 256>>>(kq, M);

    int gblocks = (N + 63) / 64;
    // x = relu(bn2(h2)) @ W3 + b3 + feats
    gemm_kernel<1><<<gblocks, 256, GEMM_SMEM_BYTES>>>(h2p, W3, b3, xp, feats, g2, b2, N);
    // q = l2norm16(x @ Wq + bq)
    gemm_kernel<2><<<gblocks, 256, GEMM_SMEM_BYTES>>>(xp, Wq, bq, qp, nullptr, nullptr, nullptr, N);
    // v = x @ Wv + bv
    gemm_kernel<0><<<gblocks, 256, GEMM_SMEM_BYTES>>>(xp, Wv, bv, vp, nullptr, nullptr, nullptr, N);

    // attention: segment gather, no atomics
    gather_kernel<<<(N + 7) / 8, 256>>>(N);

    // out = acc @ Wo + bo
    gemm_kernel<0><<<gblocks, 256, GEMM_SMEM_BYTES>>>(ap, Wo, bo, (float*)d_out,
                                                      nullptr, nullptr, nullptr, N);
}